// round 1
// baseline (speedup 1.0000x reference)
#include <cuda_runtime.h>
#include <math.h>

#define T_LEN   1024
#define DM      512
#define KF      24
#define NH      8
#define HD      64
#define BB      2
#define CHUNK   64
#define NCHUNK  (T_LEN / CHUNK)   // 16
#define NBH     (BB * NH)         // 16

// ---------------- scratch (device globals; no allocation allowed) -----------
__device__ float g_phi[T_LEN * DM];
__device__ float g_uproj[BB * T_LEN * DM];
__device__ float g_z[BB * T_LEN * DM];
__device__ float g_xt[BB * T_LEN * DM];
__device__ float g_Q[NBH * T_LEN * HD];
__device__ float g_Kb[NBH * T_LEN * HD];
__device__ float g_V[NBH * T_LEN * HD];
__device__ float g_gate[BB * T_LEN * DM];
__device__ float g_G[NBH * NCHUNK * HD * HD];
__device__ float g_H[NBH * NCHUNK * HD * HD];
__device__ float g_Y[BB * T_LEN * DM];
__device__ float g_comb[BB * T_LEN * DM];

// ---------------- activations ----------------------------------------------
__device__ __forceinline__ float gelu_tanh(float x) {
    const float c0 = 0.7978845608028654f; // sqrt(2/pi)
    float inner = c0 * (x + 0.044715f * x * x * x);
    return 0.5f * x * (1.0f + tanhf(inner));
}
__device__ __forceinline__ float sigmoidf_(float x) {
    return 1.0f / (1.0f + expf(-x));
}

// ---------------- K0: phi_proj = stu_filters(1024x24) @ M_filters(24x512) ---
__global__ __launch_bounds__(256) void phi_kernel(const float* __restrict__ f,
                                                  const float* __restrict__ Mf) {
    __shared__ float sf[KF];
    int t = blockIdx.x;
    if (threadIdx.x < KF) sf[threadIdx.x] = f[t * KF + threadIdx.x];
    __syncthreads();
    for (int r = threadIdx.x; r < DM; r += 256) {
        float acc = 0.f;
#pragma unroll
        for (int k = 0; k < KF; k++) acc += sf[k] * Mf[k * DM + r];
        g_phi[t * DM + r] = acc;
    }
}

// ---------------- generic SGEMM: C = A(MxK) @ op(B) + bias, activation ------
// BM=128, BN=64, BK=16, TM=8, TN=4, 256 threads.
// TRANSB: B stored as (N x K) row-major (i.e. x @ W^T).
// ACT: 0 none, 1 gelu, 2 sigmoid.
// OUTMODE: 0 row-major C[M,N]; 1 scatter into (b,h,t,hd) head layout.
template <int TRANSB, int ACT, int OUTMODE>
__global__ __launch_bounds__(256) void sgemm_kernel(const float* __restrict__ A,
                                                    const float* __restrict__ Bm,
                                                    const float* __restrict__ bias,
                                                    float* __restrict__ C,
                                                    int M, int N, int K) {
    __shared__ float As[16][128];
    __shared__ float Bs[16][64];
    int tid = threadIdx.x;
    int tx = tid & 15, ty = tid >> 4;
    int brow = blockIdx.y * 128, bcol = blockIdx.x * 64;
    float acc[8][4];
#pragma unroll
    for (int i = 0; i < 8; i++)
#pragma unroll
        for (int j = 0; j < 4; j++) acc[i][j] = 0.f;

    for (int kt = 0; kt < K; kt += 16) {
        // A tile: 128 x 16 (2 float4 per thread)
        {
            int row = tid >> 1;
            int kb = (tid & 1) * 8;
            const float4* ap = reinterpret_cast<const float4*>(&A[(size_t)(brow + row) * K + kt + kb]);
            float4 a0 = ap[0];
            float4 a1 = ap[1];
            As[kb + 0][row] = a0.x; As[kb + 1][row] = a0.y;
            As[kb + 2][row] = a0.z; As[kb + 3][row] = a0.w;
            As[kb + 4][row] = a1.x; As[kb + 5][row] = a1.y;
            As[kb + 6][row] = a1.z; As[kb + 7][row] = a1.w;
        }
        if (TRANSB) {
            int nrow = tid >> 2;
            int kb = (tid & 3) * 4;
            float4 w = *reinterpret_cast<const float4*>(&Bm[(size_t)(bcol + nrow) * K + kt + kb]);
            Bs[kb + 0][nrow] = w.x; Bs[kb + 1][nrow] = w.y;
            Bs[kb + 2][nrow] = w.z; Bs[kb + 3][nrow] = w.w;
        } else {
            int krow = tid >> 4;
            int nb = (tid & 15) * 4;
            float4 bv = *reinterpret_cast<const float4*>(&Bm[(size_t)(kt + krow) * N + bcol + nb]);
            *reinterpret_cast<float4*>(&Bs[krow][nb]) = bv;
        }
        __syncthreads();
#pragma unroll
        for (int kk = 0; kk < 16; kk++) {
            float ra[8], rb[4];
#pragma unroll
            for (int i = 0; i < 8; i++) ra[i] = As[kk][ty * 8 + i];
#pragma unroll
            for (int j = 0; j < 4; j++) rb[j] = Bs[kk][tx * 4 + j];
#pragma unroll
            for (int i = 0; i < 8; i++)
#pragma unroll
                for (int j = 0; j < 4; j++) acc[i][j] += ra[i] * rb[j];
        }
        __syncthreads();
    }

#pragma unroll
    for (int i = 0; i < 8; i++) {
#pragma unroll
        for (int j = 0; j < 4; j++) {
            int row = brow + ty * 8 + i;
            int col = bcol + tx * 4 + j;
            float v = acc[i][j];
            if (bias) v += bias[col];
            if (ACT == 1) v = gelu_tanh(v);
            if (ACT == 2) v = sigmoidf_(v);
            if (OUTMODE == 0) {
                C[(size_t)row * N + col] = v;
            } else {
                int b = row >> 10, t = row & 1023;
                int h = col >> 6, d = col & 63;
                C[(((size_t)(b * NH + h)) * T_LEN + t) * HD + d] = v;
            }
        }
    }
}

// ---------------- K2: even-tap causal conv: z = 2 * sum_{j even<=t} v[j]u[t-j]
__global__ __launch_bounds__(128) void conv_kernel() {
    __shared__ float su[T_LEN];
    __shared__ float sv[T_LEN];
    int r = blockIdx.x, b = blockIdx.y;
    const float* U = g_uproj + (size_t)b * T_LEN * DM + r;
    const float* V = g_phi + r;
    for (int t = threadIdx.x; t < T_LEN; t += 128) {
        su[t] = U[(size_t)t * DM];
        sv[t] = V[(size_t)t * DM];
    }
    __syncthreads();
    int tid = threadIdx.x;
    float acc[8] = {0.f, 0.f, 0.f, 0.f, 0.f, 0.f, 0.f, 0.f};
    for (int j = 0; j < T_LEN; j += 2) {
        float vj = sv[j];
#pragma unroll
        for (int k = 0; k < 8; k++) {
            int s = tid + k * 128 - j;
            if (s >= 0) acc[k] += vj * su[s];
        }
    }
#pragma unroll
    for (int k = 0; k < 8; k++) {
        int t = tid + k * 128;
        g_z[((size_t)b * T_LEN + t) * DM + r] = 2.f * acc[k];
    }
}

// ---------------- K3: LayerNorm over last dim (512) -------------------------
__global__ __launch_bounds__(256) void ln_kernel(const float* __restrict__ w,
                                                 const float* __restrict__ bparm) {
    __shared__ float red[9];
    int row = blockIdx.x;
    const float* xr = g_z + (size_t)row * DM;
    float v0 = xr[threadIdx.x];
    float v1 = xr[threadIdx.x + 256];
    float s = v0 + v1;
#pragma unroll
    for (int o = 16; o > 0; o >>= 1) s += __shfl_xor_sync(0xffffffffu, s, o);
    if ((threadIdx.x & 31) == 0) red[threadIdx.x >> 5] = s;
    __syncthreads();
    if (threadIdx.x == 0) {
        float t = 0.f;
        for (int i = 0; i < 8; i++) t += red[i];
        red[8] = t;
    }
    __syncthreads();
    float mu = red[8] * (1.0f / DM);
    __syncthreads();
    float d0 = v0 - mu, d1 = v1 - mu;
    float s2 = d0 * d0 + d1 * d1;
#pragma unroll
    for (int o = 16; o > 0; o >>= 1) s2 += __shfl_xor_sync(0xffffffffu, s2, o);
    if ((threadIdx.x & 31) == 0) red[threadIdx.x >> 5] = s2;
    __syncthreads();
    if (threadIdx.x == 0) {
        float t = 0.f;
        for (int i = 0; i < 8; i++) t += red[i];
        red[8] = t;
    }
    __syncthreads();
    float var = red[8] * (1.0f / DM);
    float inv = rsqrtf(var + 1e-5f);
    g_xt[(size_t)row * DM + threadIdx.x] = d0 * inv * w[threadIdx.x] + bparm[threadIdx.x];
    g_xt[(size_t)row * DM + threadIdx.x + 256] =
        d1 * inv * w[threadIdx.x + 256] + bparm[threadIdx.x + 256];
}

// ---------------- K5: per-chunk state G_c = V_c^T K_c (64x64) ---------------
__global__ __launch_bounds__(256) void chunkstate_kernel() {
    __shared__ float sV[CHUNK * HD];
    __shared__ float sK[CHUNK * HD];
    int c = blockIdx.x, bh = blockIdx.y;
    const float4* Vp = reinterpret_cast<const float4*>(g_V + ((size_t)bh * T_LEN + c * CHUNK) * HD);
    const float4* Kp = reinterpret_cast<const float4*>(g_Kb + ((size_t)bh * T_LEN + c * CHUNK) * HD);
    for (int i = threadIdx.x; i < CHUNK * HD / 4; i += 256) {
        reinterpret_cast<float4*>(sV)[i] = Vp[i];
        reinterpret_cast<float4*>(sK)[i] = Kp[i];
    }
    __syncthreads();
    int p0 = (threadIdx.x >> 4) * 4, n0 = (threadIdx.x & 15) * 4;
    float acc[4][4];
#pragma unroll
    for (int i = 0; i < 4; i++)
#pragma unroll
        for (int j = 0; j < 4; j++) acc[i][j] = 0.f;
    for (int s = 0; s < CHUNK; s++) {
        float rv[4], rk[4];
#pragma unroll
        for (int i = 0; i < 4; i++) rv[i] = sV[s * HD + p0 + i];
#pragma unroll
        for (int j = 0; j < 4; j++) rk[j] = sK[s * HD + n0 + j];
#pragma unroll
        for (int i = 0; i < 4; i++)
#pragma unroll
            for (int j = 0; j < 4; j++) acc[i][j] += rv[i] * rk[j];
    }
    float* Gp = g_G + ((size_t)bh * NCHUNK + c) * HD * HD;
#pragma unroll
    for (int i = 0; i < 4; i++)
#pragma unroll
        for (int j = 0; j < 4; j++) Gp[(p0 + i) * HD + n0 + j] = acc[i][j];
}

// ---------------- K5b: exclusive prefix over chunks -------------------------
__global__ __launch_bounds__(256) void prefix_kernel() {
    int bh = blockIdx.x;
    for (int slot = threadIdx.x; slot < HD * HD; slot += 256) {
        float run = 0.f;
        for (int c = 0; c < NCHUNK; c++) {
            size_t idx = ((size_t)bh * NCHUNK + c) * HD * HD + slot;
            g_H[idx] = run;
            run += g_G[idx];
        }
    }
}

// ---------------- K6: Y_c = tril(Q_c V_c^T) K_c + Q_c H_c -------------------
__global__ __launch_bounds__(256) void attn_kernel() {
    __shared__ float sQ[CHUNK * HD];      // Q [t][p]
    __shared__ float sB[CHUNK * HD];      // phase1: V^T [p][t], phase2: K [t][n]
    __shared__ float sS[CHUNK * CHUNK];   // masked scores
    int c = blockIdx.x, bh = blockIdx.y;
    int b = bh / NH, h = bh % NH;
    const float* Qp = g_Q + ((size_t)bh * T_LEN + c * CHUNK) * HD;
    const float* Vp = g_V + ((size_t)bh * T_LEN + c * CHUNK) * HD;
    const float* Kp = g_Kb + ((size_t)bh * T_LEN + c * CHUNK) * HD;

    for (int i = threadIdx.x; i < CHUNK * HD; i += 256) {
        int t = i / HD, p = i % HD;
        sQ[i] = Qp[i];
        sB[p * CHUNK + t] = Vp[i];   // V transposed
    }
    __syncthreads();

    int i0 = (threadIdx.x >> 4) * 4, j0 = (threadIdx.x & 15) * 4;
    float acc[4][4];
#pragma unroll
    for (int a = 0; a < 4; a++)
#pragma unroll
        for (int bb2 = 0; bb2 < 4; bb2++) acc[a][bb2] = 0.f;
    for (int p = 0; p < HD; p++) {
        float rq[4], rv[4];
#pragma unroll
        for (int a = 0; a < 4; a++) rq[a] = sQ[(i0 + a) * HD + p];
#pragma unroll
        for (int a = 0; a < 4; a++) rv[a] = sB[p * CHUNK + j0 + a];
#pragma unroll
        for (int a = 0; a < 4; a++)
#pragma unroll
            for (int bb2 = 0; bb2 < 4; bb2++) acc[a][bb2] += rq[a] * rv[bb2];
    }
#pragma unroll
    for (int a = 0; a < 4; a++)
#pragma unroll
        for (int bb2 = 0; bb2 < 4; bb2++)
            sS[(i0 + a) * CHUNK + j0 + bb2] = (j0 + bb2 <= i0 + a) ? acc[a][bb2] : 0.f;
    __syncthreads();

    for (int i = threadIdx.x; i < CHUNK * HD; i += 256) sB[i] = Kp[i];
    __syncthreads();

    float acc2[4][4];
#pragma unroll
    for (int a = 0; a < 4; a++)
#pragma unroll
        for (int bb2 = 0; bb2 < 4; bb2++) acc2[a][bb2] = 0.f;
    for (int j = 0; j < CHUNK; j++) {
        float rs[4], rk[4];
#pragma unroll
        for (int a = 0; a < 4; a++) rs[a] = sS[(i0 + a) * CHUNK + j];
#pragma unroll
        for (int a = 0; a < 4; a++) rk[a] = sB[j * HD + j0 + a];
#pragma unroll
        for (int a = 0; a < 4; a++)
#pragma unroll
            for (int bb2 = 0; bb2 < 4; bb2++) acc2[a][bb2] += rs[a] * rk[bb2];
    }
    const float* Hp = g_H + ((size_t)bh * NCHUNK + c) * HD * HD;
    for (int p = 0; p < HD; p++) {
        float rq[4], rh[4];
#pragma unroll
        for (int a = 0; a < 4; a++) rq[a] = sQ[(i0 + a) * HD + p];
#pragma unroll
        for (int a = 0; a < 4; a++) rh[a] = Hp[p * HD + j0 + a];
#pragma unroll
        for (int a = 0; a < 4; a++)
#pragma unroll
            for (int bb2 = 0; bb2 < 4; bb2++) acc2[a][bb2] += rq[a] * rh[bb2];
    }
#pragma unroll
    for (int a = 0; a < 4; a++) {
        int t = c * CHUNK + i0 + a;
#pragma unroll
        for (int bb2 = 0; bb2 < 4; bb2++)
            g_Y[((size_t)b * T_LEN + t) * DM + h * HD + j0 + bb2] = acc2[a][bb2];
    }
}

// ---------------- K7: comb = gate*Y + (1-gate)*x_tilde ----------------------
__global__ __launch_bounds__(256) void combine_kernel() {
    int i = blockIdx.x * 256 + threadIdx.x;
    float g = g_gate[i];
    g_comb[i] = g * g_Y[i] + (1.f - g) * g_xt[i];
}

// ---------------- host launcher ---------------------------------------------
extern "C" void kernel_launch(void* const* d_in, const int* in_sizes, int n_in,
                              void* d_out, int out_size) {
    const float* x   = (const float*)d_in[0];
    const float* flt = (const float*)d_in[1];
    const float* Mi  = (const float*)d_in[2];
    const float* Mf  = (const float*)d_in[3];
    const float* Wq  = (const float*)d_in[4];
    const float* bq  = (const float*)d_in[5];
    const float* Wk  = (const float*)d_in[6];
    const float* bk  = (const float*)d_in[7];
    const float* Wv  = (const float*)d_in[8];
    const float* bv  = (const float*)d_in[9];
    const float* Wg  = (const float*)d_in[10];
    const float* bg  = (const float*)d_in[11];
    const float* Wo  = (const float*)d_in[12];
    const float* bo  = (const float*)d_in[13];
    const float* lnw = (const float*)d_in[14];
    const float* lnb = (const float*)d_in[15];
    float* out = (float*)d_out;

    float *uproj, *Qb, *Kb, *Vb, *gate, *comb;
    cudaGetSymbolAddress((void**)&uproj, g_uproj);
    cudaGetSymbolAddress((void**)&Qb, g_Q);
    cudaGetSymbolAddress((void**)&Kb, g_Kb);
    cudaGetSymbolAddress((void**)&Vb, g_V);
    cudaGetSymbolAddress((void**)&gate, g_gate);
    cudaGetSymbolAddress((void**)&comb, g_comb);

    const int M = BB * T_LEN;  // 2048
    dim3 ggrid(DM / 64, M / 128);  // (8,16)

    // STU branch
    phi_kernel<<<T_LEN, 256>>>(flt, Mf);
    sgemm_kernel<0, 0, 0><<<ggrid, 256>>>(x, Mi, nullptr, uproj, M, DM, DM);
    conv_kernel<<<dim3(DM, BB), 128>>>();
    ln_kernel<<<M, 256>>>(lnw, lnb);

    // projections
    sgemm_kernel<1, 1, 1><<<ggrid, 256>>>(x, Wq, bq, Qb, M, DM, DM);
    sgemm_kernel<1, 1, 1><<<ggrid, 256>>>(x, Wk, bk, Kb, M, DM, DM);
    sgemm_kernel<1, 1, 1><<<ggrid, 256>>>(x, Wv, bv, Vb, M, DM, DM);
    sgemm_kernel<1, 2, 0><<<ggrid, 256>>>(x, Wg, bg, gate, M, DM, DM);

    // chunked linear attention
    chunkstate_kernel<<<dim3(NCHUNK, NBH), 256>>>();
    prefix_kernel<<<NBH, 256>>>();
    attn_kernel<<<dim3(NCHUNK, NBH), 256>>>();

    // combine + output projection
    combine_kernel<<<(BB * T_LEN * DM) / 256, 256>>>();
    sgemm_kernel<1, 0, 0><<<ggrid, 256>>>(comb, Wo, bo, out, M, DM, DM);
}

// round 2
// speedup vs baseline: 1.0747x; 1.0747x over previous
#include <cuda_runtime.h>
#include <math.h>
#include <stdint.h>

#define T_LEN   1024
#define DM      512
#define KF      24
#define NH      8
#define HD      64
#define BB      2
#define CHUNK   64
#define NCHUNK  (T_LEN / CHUNK)   // 16
#define NBH     (BB * NH)         // 16

// ---------------- scratch (device globals; no allocation allowed) -----------
__device__ float g_phi[T_LEN * DM];
__device__ float g_uproj[BB * T_LEN * DM];
__device__ float g_z[BB * T_LEN * DM];
__device__ float g_xt[BB * T_LEN * DM];
__device__ float g_Q[NBH * T_LEN * HD];
__device__ float g_Kb[NBH * T_LEN * HD];
__device__ float g_V[NBH * T_LEN * HD];
__device__ float g_gate[BB * T_LEN * DM];
__device__ float g_G[NBH * NCHUNK * HD * HD];
__device__ float g_H[NBH * NCHUNK * HD * HD];
__device__ float g_Y[BB * T_LEN * DM];
__device__ float g_comb[BB * T_LEN * DM];
__device__ float g_Wcat[4 * DM * DM];   // packed Wq|Wk|Wv|Wg, each [512][512]
__device__ float g_bcat[4 * DM];

// ---------------- activations ----------------------------------------------
__device__ __forceinline__ float gelu_tanh(float x) {
    const float c0 = 0.7978845608028654f; // sqrt(2/pi)
    float inner = c0 * (x + 0.044715f * x * x * x);
    return 0.5f * x * (1.0f + tanhf(inner));
}
__device__ __forceinline__ float sigmoidf_(float x) {
    return 1.0f / (1.0f + expf(-x));
}

// ---------------- tf32 helpers ----------------------------------------------
__device__ __forceinline__ void split_tf32(float x, float& hi, float& lo) {
    uint32_t h;
    asm("cvt.rna.tf32.f32 %0, %1;" : "=r"(h) : "f"(x));
    float hf = __uint_as_float(h);
    float r = x - hf;
    uint32_t l;
    asm("cvt.rna.tf32.f32 %0, %1;" : "=r"(l) : "f"(r));
    hi = hf;
    lo = __uint_as_float(l);
}

__device__ __forceinline__ void mma8(float* d, const uint32_t* a, const uint32_t* b) {
    asm volatile(
        "mma.sync.aligned.m16n8k8.row.col.f32.tf32.tf32.f32 "
        "{%0,%1,%2,%3}, {%4,%5,%6,%7}, {%8,%9}, {%0,%1,%2,%3};"
        : "+f"(d[0]), "+f"(d[1]), "+f"(d[2]), "+f"(d[3])
        : "r"(a[0]), "r"(a[1]), "r"(a[2]), "r"(a[3]), "r"(b[0]), "r"(b[1]));
}

// ---------------- K0: phi_proj = stu_filters(1024x24) @ M_filters(24x512) ---
__global__ __launch_bounds__(256) void phi_kernel(const float* __restrict__ f,
                                                  const float* __restrict__ Mf) {
    __shared__ float sf[KF];
    int t = blockIdx.x;
    if (threadIdx.x < KF) sf[threadIdx.x] = f[t * KF + threadIdx.x];
    __syncthreads();
    for (int r = threadIdx.x; r < DM; r += 256) {
        float acc = 0.f;
#pragma unroll
        for (int k = 0; k < KF; k++) acc += sf[k] * Mf[k * DM + r];
        g_phi[t * DM + r] = acc;
    }
}

// ---------------- repack: Wq|Wk|Wv|Wg -> g_Wcat, biases -> g_bcat -----------
__global__ __launch_bounds__(256) void repack_kernel(const float* __restrict__ Wq,
                                                     const float* __restrict__ Wk,
                                                     const float* __restrict__ Wv,
                                                     const float* __restrict__ Wg,
                                                     const float* __restrict__ bq,
                                                     const float* __restrict__ bk,
                                                     const float* __restrict__ bv,
                                                     const float* __restrict__ bg) {
    int i = blockIdx.x * 256 + threadIdx.x;      // 0 .. 4*2^18-1
    int seg = i >> 18;
    int off = i & ((1 << 18) - 1);
    const float* W = (seg == 0) ? Wq : (seg == 1) ? Wk : (seg == 2) ? Wv : Wg;
    g_Wcat[i] = W[off];
    if (i < 4 * DM) {
        int s2 = i >> 9, o2 = i & (DM - 1);
        const float* bp = (s2 == 0) ? bq : (s2 == 1) ? bk : (s2 == 2) ? bv : bg;
        g_bcat[i] = bp[o2];
    }
}

// ---------------- split-tf32 tensor-core GEMM --------------------------------
// C(MxN) = A(MxK) @ op(B)  [+bias][+activation/scatter epilogue]
// BM=128, BN=64, BK=16. 256 threads = 8 warps (4x2), warp tile 32x32.
// TRANSB: B is (N x K) row-major. EPI: 0 plain (+bias if non-null), 1 fused QKVG.
template <int EPI>
__device__ __forceinline__ void epi_store(int row, int col, float v,
                                          const float* bias, float* C, int N) {
    if (EPI == 0) {
        if (bias) v += bias[col];
        C[(size_t)row * N + col] = v;
    } else {
        v += g_bcat[col];
        int seg = col >> 9, cc = col & (DM - 1);
        int b = row >> 10, t = row & (T_LEN - 1);
        if (seg == 3) {
            g_gate[(size_t)row * DM + cc] = sigmoidf_(v);
        } else {
            float gv = gelu_tanh(v);
            float* P = (seg == 0) ? g_Q : (seg == 1) ? g_Kb : g_V;
            P[(((size_t)(b * NH + (cc >> 6))) * T_LEN + t) * HD + (cc & 63)] = gv;
        }
    }
}

template <int TRANSB, int EPI>
__global__ __launch_bounds__(256) void mma_gemm(const float* __restrict__ A,
                                                const float* __restrict__ B,
                                                const float* __restrict__ bias,
                                                float* __restrict__ C,
                                                int M, int N, int K) {
    __shared__ float Ah[16][136];
    __shared__ float Al[16][136];
    __shared__ float Bh[16][72];
    __shared__ float Bl[16][72];

    const int tid = threadIdx.x;
    const int lane = tid & 31, wid = tid >> 5;
    const int wm = wid & 3, wn = wid >> 2;          // 4 x 2 warps
    const int brow = blockIdx.y * 128, bcol = blockIdx.x * 64;
    const int c = lane & 3, r = lane >> 2;

    float d[2][4][4];
#pragma unroll
    for (int mt = 0; mt < 2; mt++)
#pragma unroll
        for (int nt = 0; nt < 4; nt++)
#pragma unroll
            for (int e = 0; e < 4; e++) d[mt][nt][e] = 0.f;

    for (int kt = 0; kt < K; kt += 16) {
        // A tile: 128 x 16 (512 float4s, 2 per thread)
#pragma unroll
        for (int q = 0; q < 2; q++) {
            int idx = tid * 2 + q;
            int row = idx >> 2, k4 = (idx & 3) * 4;
            float4 a = *reinterpret_cast<const float4*>(&A[(size_t)(brow + row) * K + kt + k4]);
            float h, l;
            split_tf32(a.x, h, l); Ah[k4 + 0][row] = h; Al[k4 + 0][row] = l;
            split_tf32(a.y, h, l); Ah[k4 + 1][row] = h; Al[k4 + 1][row] = l;
            split_tf32(a.z, h, l); Ah[k4 + 2][row] = h; Al[k4 + 2][row] = l;
            split_tf32(a.w, h, l); Ah[k4 + 3][row] = h; Al[k4 + 3][row] = l;
        }
        // B tile: 64 x 16 (256 float4s, 1 per thread)
        if (TRANSB) {
            int nrow = tid >> 2, k4 = (tid & 3) * 4;
            float4 w = *reinterpret_cast<const float4*>(&B[(size_t)(bcol + nrow) * K + kt + k4]);
            float h, l;
            split_tf32(w.x, h, l); Bh[k4 + 0][nrow] = h; Bl[k4 + 0][nrow] = l;
            split_tf32(w.y, h, l); Bh[k4 + 1][nrow] = h; Bl[k4 + 1][nrow] = l;
            split_tf32(w.z, h, l); Bh[k4 + 2][nrow] = h; Bl[k4 + 2][nrow] = l;
            split_tf32(w.w, h, l); Bh[k4 + 3][nrow] = h; Bl[k4 + 3][nrow] = l;
        } else {
            int krow = tid >> 4, n4 = (tid & 15) * 4;
            float4 w = *reinterpret_cast<const float4*>(&B[(size_t)(kt + krow) * N + bcol + n4]);
            float h, l;
            split_tf32(w.x, h, l); Bh[krow][n4 + 0] = h; Bl[krow][n4 + 0] = l;
            split_tf32(w.y, h, l); Bh[krow][n4 + 1] = h; Bl[krow][n4 + 1] = l;
            split_tf32(w.z, h, l); Bh[krow][n4 + 2] = h; Bl[krow][n4 + 2] = l;
            split_tf32(w.w, h, l); Bh[krow][n4 + 3] = h; Bl[krow][n4 + 3] = l;
        }
        __syncthreads();

#pragma unroll
        for (int ks = 0; ks < 2; ks++) {
            int kb = ks * 8;
            uint32_t ah[2][4], al[2][4], bh[4][2], bl[4][2];
#pragma unroll
            for (int mt = 0; mt < 2; mt++) {
                int m0 = wm * 32 + mt * 16 + r;
                ah[mt][0] = __float_as_uint(Ah[kb + c][m0]);
                ah[mt][1] = __float_as_uint(Ah[kb + c][m0 + 8]);
                ah[mt][2] = __float_as_uint(Ah[kb + c + 4][m0]);
                ah[mt][3] = __float_as_uint(Ah[kb + c + 4][m0 + 8]);
                al[mt][0] = __float_as_uint(Al[kb + c][m0]);
                al[mt][1] = __float_as_uint(Al[kb + c][m0 + 8]);
                al[mt][2] = __float_as_uint(Al[kb + c + 4][m0]);
                al[mt][3] = __float_as_uint(Al[kb + c + 4][m0 + 8]);
            }
#pragma unroll
            for (int nt = 0; nt < 4; nt++) {
                int n0 = wn * 32 + nt * 8 + r;
                bh[nt][0] = __float_as_uint(Bh[kb + c][n0]);
                bh[nt][1] = __float_as_uint(Bh[kb + c + 4][n0]);
                bl[nt][0] = __float_as_uint(Bl[kb + c][n0]);
                bl[nt][1] = __float_as_uint(Bl[kb + c + 4][n0]);
            }
#pragma unroll
            for (int mt = 0; mt < 2; mt++)
#pragma unroll
                for (int nt = 0; nt < 4; nt++) {
                    mma8(d[mt][nt], ah[mt], bh[nt]);
                    mma8(d[mt][nt], ah[mt], bl[nt]);
                    mma8(d[mt][nt], al[mt], bh[nt]);
                }
        }
        __syncthreads();
    }

    // epilogue
    const int c2 = (lane & 3) * 2;
#pragma unroll
    for (int mt = 0; mt < 2; mt++) {
#pragma unroll
        for (int nt = 0; nt < 4; nt++) {
            int row0 = brow + wm * 32 + mt * 16 + r;
            int col0 = bcol + wn * 32 + nt * 8 + c2;
            epi_store<EPI>(row0,     col0,     d[mt][nt][0], bias, C, N);
            epi_store<EPI>(row0,     col0 + 1, d[mt][nt][1], bias, C, N);
            epi_store<EPI>(row0 + 8, col0,     d[mt][nt][2], bias, C, N);
            epi_store<EPI>(row0 + 8, col0 + 1, d[mt][nt][3], bias, C, N);
        }
    }
}

// ---------------- K2: even-tap causal conv: z = 2 * sum_{j even<=t} v[j]u[t-j]
__global__ __launch_bounds__(128) void conv_kernel() {
    __shared__ float su[T_LEN];
    __shared__ float sv[T_LEN];
    int r = blockIdx.x, b = blockIdx.y;
    const float* U = g_uproj + (size_t)b * T_LEN * DM + r;
    const float* V = g_phi + r;
    for (int t = threadIdx.x; t < T_LEN; t += 128) {
        su[t] = U[(size_t)t * DM];
        sv[t] = V[(size_t)t * DM];
    }
    __syncthreads();
    int tid = threadIdx.x;
    float acc[8] = {0.f, 0.f, 0.f, 0.f, 0.f, 0.f, 0.f, 0.f};
    for (int j = 0; j < T_LEN; j += 2) {
        float vj = sv[j];
#pragma unroll
        for (int k = 0; k < 8; k++) {
            int s = tid + k * 128 - j;
            if (s >= 0) acc[k] += vj * su[s];
        }
    }
#pragma unroll
    for (int k = 0; k < 8; k++) {
        int t = tid + k * 128;
        g_z[((size_t)b * T_LEN + t) * DM + r] = 2.f * acc[k];
    }
}

// ---------------- K3: LayerNorm over last dim (512) -------------------------
__global__ __launch_bounds__(256) void ln_kernel(const float* __restrict__ w,
                                                 const float* __restrict__ bparm) {
    __shared__ float red[9];
    int row = blockIdx.x;
    const float* xr = g_z + (size_t)row * DM;
    float v0 = xr[threadIdx.x];
    float v1 = xr[threadIdx.x + 256];
    float s = v0 + v1;
#pragma unroll
    for (int o = 16; o > 0; o >>= 1) s += __shfl_xor_sync(0xffffffffu, s, o);
    if ((threadIdx.x & 31) == 0) red[threadIdx.x >> 5] = s;
    __syncthreads();
    if (threadIdx.x == 0) {
        float t = 0.f;
        for (int i = 0; i < 8; i++) t += red[i];
        red[8] = t;
    }
    __syncthreads();
    float mu = red[8] * (1.0f / DM);
    __syncthreads();
    float d0 = v0 - mu, d1 = v1 - mu;
    float s2 = d0 * d0 + d1 * d1;
#pragma unroll
    for (int o = 16; o > 0; o >>= 1) s2 += __shfl_xor_sync(0xffffffffu, s2, o);
    if ((threadIdx.x & 31) == 0) red[threadIdx.x >> 5] = s2;
    __syncthreads();
    if (threadIdx.x == 0) {
        float t = 0.f;
        for (int i = 0; i < 8; i++) t += red[i];
        red[8] = t;
    }
    __syncthreads();
    float var = red[8] * (1.0f / DM);
    float inv = rsqrtf(var + 1e-5f);
    g_xt[(size_t)row * DM + threadIdx.x] = d0 * inv * w[threadIdx.x] + bparm[threadIdx.x];
    g_xt[(size_t)row * DM + threadIdx.x + 256] =
        d1 * inv * w[threadIdx.x + 256] + bparm[threadIdx.x + 256];
}

// ---------------- K5: per-chunk state G_c = V_c^T K_c (64x64) ---------------
__global__ __launch_bounds__(256) void chunkstate_kernel() {
    __shared__ float sV[CHUNK * HD];
    __shared__ float sK[CHUNK * HD];
    int c = blockIdx.x, bh = blockIdx.y;
    const float4* Vp = reinterpret_cast<const float4*>(g_V + ((size_t)bh * T_LEN + c * CHUNK) * HD);
    const float4* Kp = reinterpret_cast<const float4*>(g_Kb + ((size_t)bh * T_LEN + c * CHUNK) * HD);
    for (int i = threadIdx.x; i < CHUNK * HD / 4; i += 256) {
        reinterpret_cast<float4*>(sV)[i] = Vp[i];
        reinterpret_cast<float4*>(sK)[i] = Kp[i];
    }
    __syncthreads();
    int p0 = (threadIdx.x >> 4) * 4, n0 = (threadIdx.x & 15) * 4;
    float acc[4][4];
#pragma unroll
    for (int i = 0; i < 4; i++)
#pragma unroll
        for (int j = 0; j < 4; j++) acc[i][j] = 0.f;
    for (int s = 0; s < CHUNK; s++) {
        float rv[4], rk[4];
#pragma unroll
        for (int i = 0; i < 4; i++) rv[i] = sV[s * HD + p0 + i];
#pragma unroll
        for (int j = 0; j < 4; j++) rk[j] = sK[s * HD + n0 + j];
#pragma unroll
        for (int i = 0; i < 4; i++)
#pragma unroll
            for (int j = 0; j < 4; j++) acc[i][j] += rv[i] * rk[j];
    }
    float* Gp = g_G + ((size_t)bh * NCHUNK + c) * HD * HD;
#pragma unroll
    for (int i = 0; i < 4; i++)
#pragma unroll
        for (int j = 0; j < 4; j++) Gp[(p0 + i) * HD + n0 + j] = acc[i][j];
}

// ---------------- K5b: exclusive prefix over chunks -------------------------
__global__ __launch_bounds__(256) void prefix_kernel() {
    int bh = blockIdx.x;
    for (int slot = threadIdx.x; slot < HD * HD; slot += 256) {
        float run = 0.f;
        for (int c = 0; c < NCHUNK; c++) {
            size_t idx = ((size_t)bh * NCHUNK + c) * HD * HD + slot;
            g_H[idx] = run;
            run += g_G[idx];
        }
    }
}

// ---------------- K6: Y_c = tril(Q_c V_c^T) K_c + Q_c H_c -------------------
__global__ __launch_bounds__(256) void attn_kernel() {
    __shared__ float sQ[CHUNK * HD];
    __shared__ float sB[CHUNK * HD];
    __shared__ float sS[CHUNK * CHUNK];
    int c = blockIdx.x, bh = blockIdx.y;
    int b = bh / NH, h = bh % NH;
    const float* Qp = g_Q + ((size_t)bh * T_LEN + c * CHUNK) * HD;
    const float* Vp = g_V + ((size_t)bh * T_LEN + c * CHUNK) * HD;
    const float* Kp = g_Kb + ((size_t)bh * T_LEN + c * CHUNK) * HD;

    for (int i = threadIdx.x; i < CHUNK * HD; i += 256) {
        int t = i / HD, p = i % HD;
        sQ[i] = Qp[i];
        sB[p * CHUNK + t] = Vp[i];
    }
    __syncthreads();

    int i0 = (threadIdx.x >> 4) * 4, j0 = (threadIdx.x & 15) * 4;
    float acc[4][4];
#pragma unroll
    for (int a = 0; a < 4; a++)
#pragma unroll
        for (int bb2 = 0; bb2 < 4; bb2++) acc[a][bb2] = 0.f;
    for (int p = 0; p < HD; p++) {
        float rq[4], rv[4];
#pragma unroll
        for (int a = 0; a < 4; a++) rq[a] = sQ[(i0 + a) * HD + p];
#pragma unroll
        for (int a = 0; a < 4; a++) rv[a] = sB[p * CHUNK + j0 + a];
#pragma unroll
        for (int a = 0; a < 4; a++)
#pragma unroll
            for (int bb2 = 0; bb2 < 4; bb2++) acc[a][bb2] += rq[a] * rv[bb2];
    }
#pragma unroll
    for (int a = 0; a < 4; a++)
#pragma unroll
        for (int bb2 = 0; bb2 < 4; bb2++)
            sS[(i0 + a) * CHUNK + j0 + bb2] = (j0 + bb2 <= i0 + a) ? acc[a][bb2] : 0.f;
    __syncthreads();

    for (int i = threadIdx.x; i < CHUNK * HD; i += 256) sB[i] = Kp[i];
    __syncthreads();

    float acc2[4][4];
#pragma unroll
    for (int a = 0; a < 4; a++)
#pragma unroll
        for (int bb2 = 0; bb2 < 4; bb2++) acc2[a][bb2] = 0.f;
    for (int j = 0; j < CHUNK; j++) {
        float rs[4], rk[4];
#pragma unroll
        for (int a = 0; a < 4; a++) rs[a] = sS[(i0 + a) * CHUNK + j];
#pragma unroll
        for (int a = 0; a < 4; a++) rk[a] = sB[j * HD + j0 + a];
#pragma unroll
        for (int a = 0; a < 4; a++)
#pragma unroll
            for (int bb2 = 0; bb2 < 4; bb2++) acc2[a][bb2] += rs[a] * rk[bb2];
    }
    const float* Hp = g_H + ((size_t)bh * NCHUNK + c) * HD * HD;
    for (int p = 0; p < HD; p++) {
        float rq[4], rh[4];
#pragma unroll
        for (int a = 0; a < 4; a++) rq[a] = sQ[(i0 + a) * HD + p];
#pragma unroll
        for (int a = 0; a < 4; a++) rh[a] = Hp[p * HD + j0 + a];
#pragma unroll
        for (int a = 0; a < 4; a++)
#pragma unroll
            for (int bb2 = 0; bb2 < 4; bb2++) acc2[a][bb2] += rq[a] * rh[bb2];
    }
#pragma unroll
    for (int a = 0; a < 4; a++) {
        int t = c * CHUNK + i0 + a;
#pragma unroll
        for (int bb2 = 0; bb2 < 4; bb2++)
            g_Y[((size_t)b * T_LEN + t) * DM + h * HD + j0 + bb2] = acc2[a][bb2];
    }
}

// ---------------- K7: comb = gate*Y + (1-gate)*x_tilde ----------------------
__global__ __launch_bounds__(256) void combine_kernel() {
    int i = blockIdx.x * 256 + threadIdx.x;
    float g = g_gate[i];
    g_comb[i] = g * g_Y[i] + (1.f - g) * g_xt[i];
}

// ---------------- host launcher ---------------------------------------------
extern "C" void kernel_launch(void* const* d_in, const int* in_sizes, int n_in,
                              void* d_out, int out_size) {
    const float* x   = (const float*)d_in[0];
    const float* flt = (const float*)d_in[1];
    const float* Mi  = (const float*)d_in[2];
    const float* Mf  = (const float*)d_in[3];
    const float* Wq  = (const float*)d_in[4];
    const float* bq  = (const float*)d_in[5];
    const float* Wk  = (const float*)d_in[6];
    const float* bk  = (const float*)d_in[7];
    const float* Wv  = (const float*)d_in[8];
    const float* bv  = (const float*)d_in[9];
    const float* Wg  = (const float*)d_in[10];
    const float* bg  = (const float*)d_in[11];
    const float* Wo  = (const float*)d_in[12];
    const float* bo  = (const float*)d_in[13];
    const float* lnw = (const float*)d_in[14];
    const float* lnb = (const float*)d_in[15];
    float* out = (float*)d_out;

    float *uproj, *Wcat, *comb;
    cudaGetSymbolAddress((void**)&uproj, g_uproj);
    cudaGetSymbolAddress((void**)&Wcat, g_Wcat);
    cudaGetSymbolAddress((void**)&comb, g_comb);

    const int M = BB * T_LEN;  // 2048

    // STU branch
    phi_kernel<<<T_LEN, 256>>>(flt, Mf);
    mma_gemm<0, 0><<<dim3(DM / 64, M / 128), 256>>>(x, Mi, nullptr, uproj, M, DM, DM);
    conv_kernel<<<dim3(DM, BB), 128>>>();
    ln_kernel<<<M, 256>>>(lnw, lnb);

    // fused QKVG projection (N = 2048)
    repack_kernel<<<4 * DM * DM / 256, 256>>>(Wq, Wk, Wv, Wg, bq, bk, bv, bg);
    mma_gemm<1, 1><<<dim3(4 * DM / 64, M / 128), 256>>>(x, Wcat, nullptr, nullptr,
                                                        M, 4 * DM, DM);

    // chunked linear attention
    chunkstate_kernel<<<dim3(NCHUNK, NBH), 256>>>();
    prefix_kernel<<<NBH, 256>>>();
    attn_kernel<<<dim3(NCHUNK, NBH), 256>>>();

    // combine + output projection
    combine_kernel<<<(BB * T_LEN * DM) / 256, 256>>>();
    mma_gemm<1, 0><<<dim3(DM / 64, M / 128), 256>>>(comb, Wo, bo, out, M, DM, DM);
}

// round 3
// speedup vs baseline: 1.1776x; 1.0957x over previous
#include <cuda_runtime.h>
#include <math.h>
#include <stdint.h>

#define T_LEN   1024
#define DM      512
#define KF      24
#define NH      8
#define HD      64
#define BB      2
#define CHUNK   64
#define NCHUNK  (T_LEN / CHUNK)   // 16
#define NBH     (BB * NH)         // 16

// ---------------- scratch (device globals; no allocation allowed) -----------
__device__ float g_phi[T_LEN * DM];
__device__ float g_uproj[BB * T_LEN * DM];
__device__ float g_z[BB * T_LEN * DM];
__device__ float g_xt[BB * T_LEN * DM];
__device__ float g_Q[NBH * T_LEN * HD];
__device__ float g_Kb[NBH * T_LEN * HD];
__device__ float g_V[NBH * T_LEN * HD];
__device__ float g_gate[BB * T_LEN * DM];
__device__ float g_G[NBH * NCHUNK * HD * HD];
__device__ float g_H[NBH * NCHUNK * HD * HD];
__device__ float g_Y[BB * T_LEN * DM];
__device__ float g_Wcat[4 * DM * DM];   // packed Wq|Wk|Wv|Wg, each [512][512]
__device__ float g_bcat[4 * DM];

// ---------------- activations ----------------------------------------------
__device__ __forceinline__ float gelu_tanh(float x) {
    const float c0 = 0.7978845608028654f; // sqrt(2/pi)
    float inner = c0 * (x + 0.044715f * x * x * x);
    return 0.5f * x * (1.0f + tanhf(inner));
}
__device__ __forceinline__ float sigmoidf_(float x) {
    return 1.0f / (1.0f + expf(-x));
}

// ---------------- tf32 helpers ----------------------------------------------
__device__ __forceinline__ void split_tf32(float x, float& hi, float& lo) {
    uint32_t h;
    asm("cvt.rna.tf32.f32 %0, %1;" : "=r"(h) : "f"(x));
    float hf = __uint_as_float(h);
    float r = x - hf;
    uint32_t l;
    asm("cvt.rna.tf32.f32 %0, %1;" : "=r"(l) : "f"(r));
    hi = hf;
    lo = __uint_as_float(l);
}

__device__ __forceinline__ void mma8(float* d, const uint32_t* a, const uint32_t* b) {
    asm volatile(
        "mma.sync.aligned.m16n8k8.row.col.f32.tf32.tf32.f32 "
        "{%0,%1,%2,%3}, {%4,%5,%6,%7}, {%8,%9}, {%0,%1,%2,%3};"
        : "+f"(d[0]), "+f"(d[1]), "+f"(d[2]), "+f"(d[3])
        : "r"(a[0]), "r"(a[1]), "r"(a[2]), "r"(a[3]), "r"(b[0]), "r"(b[1]));
}

// ---------------- K0: phi_proj = stu_filters(1024x24) @ M_filters(24x512) ---
__global__ __launch_bounds__(256) void phi_kernel(const float* __restrict__ f,
                                                  const float* __restrict__ Mf) {
    __shared__ float sf[KF];
    int t = blockIdx.x;
    if (threadIdx.x < KF) sf[threadIdx.x] = f[t * KF + threadIdx.x];
    __syncthreads();
    for (int r = threadIdx.x; r < DM; r += 256) {
        float acc = 0.f;
#pragma unroll
        for (int k = 0; k < KF; k++) acc += sf[k] * Mf[k * DM + r];
        g_phi[t * DM + r] = acc;
    }
}

// ---------------- repack: Wq|Wk|Wv|Wg -> g_Wcat, biases -> g_bcat -----------
__global__ __launch_bounds__(256) void repack_kernel(const float* __restrict__ Wq,
                                                     const float* __restrict__ Wk,
                                                     const float* __restrict__ Wv,
                                                     const float* __restrict__ Wg,
                                                     const float* __restrict__ bq,
                                                     const float* __restrict__ bk,
                                                     const float* __restrict__ bv,
                                                     const float* __restrict__ bg) {
    int i = blockIdx.x * 256 + threadIdx.x;      // 0 .. 4*2^18-1
    int seg = i >> 18;
    int off = i & ((1 << 18) - 1);
    const float* W = (seg == 0) ? Wq : (seg == 1) ? Wk : (seg == 2) ? Wv : Wg;
    g_Wcat[i] = W[off];
    if (i < 4 * DM) {
        int s2 = i >> 9, o2 = i & (DM - 1);
        const float* bp = (s2 == 0) ? bq : (s2 == 1) ? bk : (s2 == 2) ? bv : bg;
        g_bcat[i] = bp[o2];
    }
}

// ---------------- split-tf32 tensor-core GEMM --------------------------------
// BM=128, BN=64, BK=16. 256 threads = 8 warps (4x2), warp tile 32x32.
// TRANSB: B is (N x K) row-major. EPI: 0 plain (+bias), 1 fused QKVG scatter.
// COMBA: A is formed on the fly as gate*Y + (1-gate)*xt (all device globals).
template <int EPI>
__device__ __forceinline__ void epi_store(int row, int col, float v,
                                          const float* bias, float* C, int N) {
    if (EPI == 0) {
        if (bias) v += bias[col];
        C[(size_t)row * N + col] = v;
    } else {
        v += g_bcat[col];
        int seg = col >> 9, cc = col & (DM - 1);
        int b = row >> 10, t = row & (T_LEN - 1);
        if (seg == 3) {
            g_gate[(size_t)row * DM + cc] = sigmoidf_(v);
        } else {
            float gv = gelu_tanh(v);
            float* P = (seg == 0) ? g_Q : (seg == 1) ? g_Kb : g_V;
            P[(((size_t)(b * NH + (cc >> 6))) * T_LEN + t) * HD + (cc & 63)] = gv;
        }
    }
}

template <int TRANSB, int EPI, int COMBA>
__global__ __launch_bounds__(256) void mma_gemm(const float* __restrict__ A,
                                                const float* __restrict__ B,
                                                const float* __restrict__ bias,
                                                float* __restrict__ C,
                                                int M, int N, int K) {
    __shared__ float Ah[16][136];
    __shared__ float Al[16][136];
    __shared__ float Bh[16][72];
    __shared__ float Bl[16][72];

    const int tid = threadIdx.x;
    const int lane = tid & 31, wid = tid >> 5;
    const int wm = wid & 3, wn = wid >> 2;          // 4 x 2 warps
    const int brow = blockIdx.y * 128, bcol = blockIdx.x * 64;
    const int c = lane & 3, r = lane >> 2;

    float d[2][4][4];
#pragma unroll
    for (int mt = 0; mt < 2; mt++)
#pragma unroll
        for (int nt = 0; nt < 4; nt++)
#pragma unroll
            for (int e = 0; e < 4; e++) d[mt][nt][e] = 0.f;

    for (int kt = 0; kt < K; kt += 16) {
        // A tile: 128 x 16 (512 float4s, 2 per thread)
#pragma unroll
        for (int q = 0; q < 2; q++) {
            int idx = tid * 2 + q;
            int row = idx >> 2, k4 = (idx & 3) * 4;
            size_t off = (size_t)(brow + row) * K + kt + k4;
            float4 a;
            if (COMBA) {
                float4 gq = *reinterpret_cast<const float4*>(&g_gate[off]);
                float4 yq = *reinterpret_cast<const float4*>(&g_Y[off]);
                float4 xq = *reinterpret_cast<const float4*>(&g_xt[off]);
                a.x = gq.x * yq.x + (1.f - gq.x) * xq.x;
                a.y = gq.y * yq.y + (1.f - gq.y) * xq.y;
                a.z = gq.z * yq.z + (1.f - gq.z) * xq.z;
                a.w = gq.w * yq.w + (1.f - gq.w) * xq.w;
            } else {
                a = *reinterpret_cast<const float4*>(&A[off]);
            }
            float h, l;
            split_tf32(a.x, h, l); Ah[k4 + 0][row] = h; Al[k4 + 0][row] = l;
            split_tf32(a.y, h, l); Ah[k4 + 1][row] = h; Al[k4 + 1][row] = l;
            split_tf32(a.z, h, l); Ah[k4 + 2][row] = h; Al[k4 + 2][row] = l;
            split_tf32(a.w, h, l); Ah[k4 + 3][row] = h; Al[k4 + 3][row] = l;
        }
        // B tile: 64 x 16 (256 float4s, 1 per thread)
        if (TRANSB) {
            int nrow = tid >> 2, k4 = (tid & 3) * 4;
            float4 w = *reinterpret_cast<const float4*>(&B[(size_t)(bcol + nrow) * K + kt + k4]);
            float h, l;
            split_tf32(w.x, h, l); Bh[k4 + 0][nrow] = h; Bl[k4 + 0][nrow] = l;
            split_tf32(w.y, h, l); Bh[k4 + 1][nrow] = h; Bl[k4 + 1][nrow] = l;
            split_tf32(w.z, h, l); Bh[k4 + 2][nrow] = h; Bl[k4 + 2][nrow] = l;
            split_tf32(w.w, h, l); Bh[k4 + 3][nrow] = h; Bl[k4 + 3][nrow] = l;
        } else {
            int krow = tid >> 4, n4 = (tid & 15) * 4;
            float4 w = *reinterpret_cast<const float4*>(&B[(size_t)(kt + krow) * N + bcol + n4]);
            float h, l;
            split_tf32(w.x, h, l); Bh[krow][n4 + 0] = h; Bl[krow][n4 + 0] = l;
            split_tf32(w.y, h, l); Bh[krow][n4 + 1] = h; Bl[krow][n4 + 1] = l;
            split_tf32(w.z, h, l); Bh[krow][n4 + 2] = h; Bl[krow][n4 + 2] = l;
            split_tf32(w.w, h, l); Bh[krow][n4 + 3] = h; Bl[krow][n4 + 3] = l;
        }
        __syncthreads();

#pragma unroll
        for (int ks = 0; ks < 2; ks++) {
            int kb = ks * 8;
            uint32_t ah[2][4], al[2][4], bh[4][2], bl[4][2];
#pragma unroll
            for (int mt = 0; mt < 2; mt++) {
                int m0 = wm * 32 + mt * 16 + r;
                ah[mt][0] = __float_as_uint(Ah[kb + c][m0]);
                ah[mt][1] = __float_as_uint(Ah[kb + c][m0 + 8]);
                ah[mt][2] = __float_as_uint(Ah[kb + c + 4][m0]);
                ah[mt][3] = __float_as_uint(Ah[kb + c + 4][m0 + 8]);
                al[mt][0] = __float_as_uint(Al[kb + c][m0]);
                al[mt][1] = __float_as_uint(Al[kb + c][m0 + 8]);
                al[mt][2] = __float_as_uint(Al[kb + c + 4][m0]);
                al[mt][3] = __float_as_uint(Al[kb + c + 4][m0 + 8]);
            }
#pragma unroll
            for (int nt = 0; nt < 4; nt++) {
                int n0 = wn * 32 + nt * 8 + r;
                bh[nt][0] = __float_as_uint(Bh[kb + c][n0]);
                bh[nt][1] = __float_as_uint(Bh[kb + c + 4][n0]);
                bl[nt][0] = __float_as_uint(Bl[kb + c][n0]);
                bl[nt][1] = __float_as_uint(Bl[kb + c + 4][n0]);
            }
#pragma unroll
            for (int mt = 0; mt < 2; mt++)
#pragma unroll
                for (int nt = 0; nt < 4; nt++) {
                    mma8(d[mt][nt], ah[mt], bh[nt]);
                    mma8(d[mt][nt], ah[mt], bl[nt]);
                    mma8(d[mt][nt], al[mt], bh[nt]);
                }
        }
        __syncthreads();
    }

    // epilogue
    const int c2 = (lane & 3) * 2;
#pragma unroll
    for (int mt = 0; mt < 2; mt++) {
#pragma unroll
        for (int nt = 0; nt < 4; nt++) {
            int row0 = brow + wm * 32 + mt * 16 + r;
            int col0 = bcol + wn * 32 + nt * 8 + c2;
            epi_store<EPI>(row0,     col0,     d[mt][nt][0], bias, C, N);
            epi_store<EPI>(row0,     col0 + 1, d[mt][nt][1], bias, C, N);
            epi_store<EPI>(row0 + 8, col0,     d[mt][nt][2], bias, C, N);
            epi_store<EPI>(row0 + 8, col0 + 1, d[mt][nt][3], bias, C, N);
        }
    }
}

// ---------------- K2: even-tap causal conv ----------------------------------
// z[b,t,r] = 2 * sum_{j even, j<=t} v[j,r] * u[b,t-j,r]
// Thread owns t_k = tid + 128k (k=0..7). j-loop split into 8 segments by the
// smallest live accumulator: segment m covers j in (tid+128(m-1), tid+128m],
// where exactly accumulators k >= m are live -> predicate-free inner loops.
__global__ __launch_bounds__(128) void conv_kernel() {
    __shared__ float su[T_LEN];
    __shared__ float sv[T_LEN];
    int r = blockIdx.x, b = blockIdx.y;
    const float* U = g_uproj + (size_t)b * T_LEN * DM + r;
    const float* V = g_phi + r;
    for (int t = threadIdx.x; t < T_LEN; t += 128) {
        su[t] = U[(size_t)t * DM];
        sv[t] = V[(size_t)t * DM];
    }
    __syncthreads();
    const int tid = threadIdx.x;
    float acc[8] = {0.f, 0.f, 0.f, 0.f, 0.f, 0.f, 0.f, 0.f};

#pragma unroll
    for (int m = 0; m < 8; m++) {
        int lo = (m == 0) ? 0 : (tid + 128 * (m - 1) + 1);
        int jlo = lo + (lo & 1);            // round up to even
        int jhi = tid + 128 * m;            // inclusive
        for (int j = jlo; j <= jhi; j += 2) {
            float vj = sv[j];
#pragma unroll
            for (int k = m; k < 8; k++) {
                acc[k] += vj * su[tid + 128 * k - j];
            }
        }
    }
#pragma unroll
    for (int k = 0; k < 8; k++) {
        int t = tid + k * 128;
        g_z[((size_t)b * T_LEN + t) * DM + r] = 2.f * acc[k];
    }
}

// ---------------- K3: LayerNorm over last dim (512), single pass ------------
__global__ __launch_bounds__(256) void ln_kernel(const float* __restrict__ w,
                                                 const float* __restrict__ bparm) {
    __shared__ float redA[8];
    __shared__ float redB[8];
    __shared__ float bc[2];
    int row = blockIdx.x;
    const float* xr = g_z + (size_t)row * DM;
    float v0 = xr[threadIdx.x];
    float v1 = xr[threadIdx.x + 256];
    float s1 = v0 + v1;
    float s2 = v0 * v0 + v1 * v1;
#pragma unroll
    for (int o = 16; o > 0; o >>= 1) {
        s1 += __shfl_xor_sync(0xffffffffu, s1, o);
        s2 += __shfl_xor_sync(0xffffffffu, s2, o);
    }
    int warp = threadIdx.x >> 5;
    if ((threadIdx.x & 31) == 0) { redA[warp] = s1; redB[warp] = s2; }
    __syncthreads();
    if (threadIdx.x < 32) {
        float a = (threadIdx.x < 8) ? redA[threadIdx.x] : 0.f;
        float bsum = (threadIdx.x < 8) ? redB[threadIdx.x] : 0.f;
#pragma unroll
        for (int o = 4; o > 0; o >>= 1) {
            a += __shfl_xor_sync(0xffffffffu, a, o);
            bsum += __shfl_xor_sync(0xffffffffu, bsum, o);
        }
        if (threadIdx.x == 0) { bc[0] = a; bc[1] = bsum; }
    }
    __syncthreads();
    float mu = bc[0] * (1.0f / DM);
    float var = bc[1] * (1.0f / DM) - mu * mu;
    float inv = rsqrtf(var + 1e-5f);
    float d0 = v0 - mu, d1 = v1 - mu;
    g_xt[(size_t)row * DM + threadIdx.x] = d0 * inv * w[threadIdx.x] + bparm[threadIdx.x];
    g_xt[(size_t)row * DM + threadIdx.x + 256] =
        d1 * inv * w[threadIdx.x + 256] + bparm[threadIdx.x + 256];
}

// ---------------- K5: per-chunk state G_c = V_c^T K_c (64x64) ---------------
__global__ __launch_bounds__(256) void chunkstate_kernel() {
    __shared__ float sV[CHUNK * HD];
    __shared__ float sK[CHUNK * HD];
    int c = blockIdx.x, bh = blockIdx.y;
    const float4* Vp = reinterpret_cast<const float4*>(g_V + ((size_t)bh * T_LEN + c * CHUNK) * HD);
    const float4* Kp = reinterpret_cast<const float4*>(g_Kb + ((size_t)bh * T_LEN + c * CHUNK) * HD);
    for (int i = threadIdx.x; i < CHUNK * HD / 4; i += 256) {
        reinterpret_cast<float4*>(sV)[i] = Vp[i];
        reinterpret_cast<float4*>(sK)[i] = Kp[i];
    }
    __syncthreads();
    int p0 = (threadIdx.x >> 4) * 4, n0 = (threadIdx.x & 15) * 4;
    float acc[4][4];
#pragma unroll
    for (int i = 0; i < 4; i++)
#pragma unroll
        for (int j = 0; j < 4; j++) acc[i][j] = 0.f;
    for (int s = 0; s < CHUNK; s++) {
        float rv[4], rk[4];
#pragma unroll
        for (int i = 0; i < 4; i++) rv[i] = sV[s * HD + p0 + i];
#pragma unroll
        for (int j = 0; j < 4; j++) rk[j] = sK[s * HD + n0 + j];
#pragma unroll
        for (int i = 0; i < 4; i++)
#pragma unroll
            for (int j = 0; j < 4; j++) acc[i][j] += rv[i] * rk[j];
    }
    float* Gp = g_G + ((size_t)bh * NCHUNK + c) * HD * HD;
#pragma unroll
    for (int i = 0; i < 4; i++)
#pragma unroll
        for (int j = 0; j < 4; j++) Gp[(p0 + i) * HD + n0 + j] = acc[i][j];
}

// ---------------- K5b: exclusive prefix over chunks -------------------------
__global__ __launch_bounds__(256) void prefix_kernel() {
    int bh = blockIdx.x;
    for (int slot = threadIdx.x; slot < HD * HD; slot += 256) {
        float run = 0.f;
        for (int c = 0; c < NCHUNK; c++) {
            size_t idx = ((size_t)bh * NCHUNK + c) * HD * HD + slot;
            g_H[idx] = run;
            run += g_G[idx];
        }
    }
}

// ---------------- K6: Y_c = tril(Q_c V_c^T) K_c + Q_c H_c -------------------
__global__ __launch_bounds__(256) void attn_kernel() {
    __shared__ float sQ[CHUNK * HD];
    __shared__ float sB[CHUNK * HD];
    __shared__ float sS[CHUNK * CHUNK];
    int c = blockIdx.x, bh = blockIdx.y;
    int b = bh / NH, h = bh % NH;
    const float* Qp = g_Q + ((size_t)bh * T_LEN + c * CHUNK) * HD;
    const float* Vp = g_V + ((size_t)bh * T_LEN + c * CHUNK) * HD;
    const float* Kp = g_Kb + ((size_t)bh * T_LEN + c * CHUNK) * HD;

    for (int i = threadIdx.x; i < CHUNK * HD; i += 256) {
        int t = i / HD, p = i % HD;
        sQ[i] = Qp[i];
        sB[p * CHUNK + t] = Vp[i];
    }
    __syncthreads();

    int i0 = (threadIdx.x >> 4) * 4, j0 = (threadIdx.x & 15) * 4;
    float acc[4][4];
#pragma unroll
    for (int a = 0; a < 4; a++)
#pragma unroll
        for (int bb2 = 0; bb2 < 4; bb2++) acc[a][bb2] = 0.f;
    for (int p = 0; p < HD; p++) {
        float rq[4], rv[4];
#pragma unroll
        for (int a = 0; a < 4; a++) rq[a] = sQ[(i0 + a) * HD + p];
#pragma unroll
        for (int a = 0; a < 4; a++) rv[a] = sB[p * CHUNK + j0 + a];
#pragma unroll
        for (int a = 0; a < 4; a++)
#pragma unroll
            for (int bb2 = 0; bb2 < 4; bb2++) acc[a][bb2] += rq[a] * rv[bb2];
    }
#pragma unroll
    for (int a = 0; a < 4; a++)
#pragma unroll
        for (int bb2 = 0; bb2 < 4; bb2++)
            sS[(i0 + a) * CHUNK + j0 + bb2] = (j0 + bb2 <= i0 + a) ? acc[a][bb2] : 0.f;
    __syncthreads();

    for (int i = threadIdx.x; i < CHUNK * HD; i += 256) sB[i] = Kp[i];
    __syncthreads();

    float acc2[4][4];
#pragma unroll
    for (int a = 0; a < 4; a++)
#pragma unroll
        for (int bb2 = 0; bb2 < 4; bb2++) acc2[a][bb2] = 0.f;
    for (int j = 0; j < CHUNK; j++) {
        float rs[4], rk[4];
#pragma unroll
        for (int a = 0; a < 4; a++) rs[a] = sS[(i0 + a) * CHUNK + j];
#pragma unroll
        for (int a = 0; a < 4; a++) rk[a] = sB[j * HD + j0 + a];
#pragma unroll
        for (int a = 0; a < 4; a++)
#pragma unroll
            for (int bb2 = 0; bb2 < 4; bb2++) acc2[a][bb2] += rs[a] * rk[bb2];
    }
    const float* Hp = g_H + ((size_t)bh * NCHUNK + c) * HD * HD;
    for (int p = 0; p < HD; p++) {
        float rq[4], rh[4];
#pragma unroll
        for (int a = 0; a < 4; a++) rq[a] = sQ[(i0 + a) * HD + p];
#pragma unroll
        for (int a = 0; a < 4; a++) rh[a] = Hp[p * HD + j0 + a];
#pragma unroll
        for (int a = 0; a < 4; a++)
#pragma unroll
            for (int bb2 = 0; bb2 < 4; bb2++) acc2[a][bb2] += rq[a] * rh[bb2];
    }
#pragma unroll
    for (int a = 0; a < 4; a++) {
        int t = c * CHUNK + i0 + a;
#pragma unroll
        for (int bb2 = 0; bb2 < 4; bb2++)
            g_Y[((size_t)b * T_LEN + t) * DM + h * HD + j0 + bb2] = acc2[a][bb2];
    }
}

// ---------------- host launcher ---------------------------------------------
extern "C" void kernel_launch(void* const* d_in, const int* in_sizes, int n_in,
                              void* d_out, int out_size) {
    const float* x   = (const float*)d_in[0];
    const float* flt = (const float*)d_in[1];
    const float* Mi  = (const float*)d_in[2];
    const float* Mf  = (const float*)d_in[3];
    const float* Wq  = (const float*)d_in[4];
    const float* bq  = (const float*)d_in[5];
    const float* Wk  = (const float*)d_in[6];
    const float* bk  = (const float*)d_in[7];
    const float* Wv  = (const float*)d_in[8];
    const float* bv  = (const float*)d_in[9];
    const float* Wg  = (const float*)d_in[10];
    const float* bg  = (const float*)d_in[11];
    const float* Wo  = (const float*)d_in[12];
    const float* bo  = (const float*)d_in[13];
    const float* lnw = (const float*)d_in[14];
    const float* lnb = (const float*)d_in[15];
    float* out = (float*)d_out;

    float *uproj, *Wcat;
    cudaGetSymbolAddress((void**)&uproj, g_uproj);
    cudaGetSymbolAddress((void**)&Wcat, g_Wcat);

    const int M = BB * T_LEN;  // 2048

    // 1-2: preprocessing (independent)
    phi_kernel<<<T_LEN, 256>>>(flt, Mf);
    repack_kernel<<<4 * DM * DM / 256, 256>>>(Wq, Wk, Wv, Wg, bq, bk, bv, bg);

    // 3: u projection (STU branch)
    mma_gemm<0, 0, 0><<<dim3(DM / 64, M / 128), 256>>>(x, Mi, nullptr, uproj, M, DM, DM);

    // 4: fused QKVG projection (N = 2048)  [profiled slot]
    mma_gemm<1, 1, 0><<<dim3(4 * DM / 64, M / 128), 256>>>(x, Wcat, nullptr, nullptr,
                                                           M, 4 * DM, DM);

    // 5-6: STU conv + layernorm
    conv_kernel<<<dim3(DM, BB), 128>>>();
    ln_kernel<<<M, 256>>>(lnw, lnb);

    // 7-9: chunked linear attention
    chunkstate_kernel<<<dim3(NCHUNK, NBH), 256>>>();
    prefix_kernel<<<NBH, 256>>>();
    attn_kernel<<<dim3(NCHUNK, NBH), 256>>>();

    // 10: output projection with fused combine (A = gate*Y + (1-gate)*xt)
    mma_gemm<1, 0, 1><<<dim3(DM / 64, M / 128), 256>>>(nullptr, Wo, bo, out, M, DM, DM);
}

// round 7
// speedup vs baseline: 2.0143x; 1.7105x over previous
#include <cuda_runtime.h>
#include <cuda_bf16.h>
#include <math.h>
#include <stdint.h>

#define T_LEN   1024
#define DM      512
#define KF      24
#define NH      8
#define HD      64
#define BB      2
#define CHUNK   64
#define NCHUNK  (T_LEN / CHUNK)   // 16
#define NBH     (BB * NH)         // 16
#define NCAT    (5 * DM)          // 2560: Q|K|V|G|U

// ---------------- scratch (device globals; no allocation allowed) -----------
__device__ float g_phiT[DM * T_LEN];           // [r][t]
__device__ float g_upT[DM * BB * T_LEN];       // [r][b*T+t]
__device__ float g_z[BB * T_LEN * DM];
__device__ float g_xt[BB * T_LEN * DM];
__device__ float g_Q[NBH * T_LEN * HD];
__device__ float g_Kb[NBH * T_LEN * HD];
__device__ float g_V[NBH * T_LEN * HD];
__device__ float g_gate[BB * T_LEN * DM];
__device__ float g_G[NBH * NCHUNK * HD * HD];
__device__ float g_H[NBH * NCHUNK * HD * HD];
__device__ float g_Y[BB * T_LEN * DM];
__device__ float g_Wcat[NCAT * DM];            // Wq|Wk|Wv|Wg|Mi^T rows
__device__ float g_bcat[4 * DM];

// ---------------- activations ----------------------------------------------
__device__ __forceinline__ float gelu_tanh(float x) {
    const float c0 = 0.7978845608028654f;
    float inner = c0 * (x + 0.044715f * x * x * x);
    return 0.5f * x * (1.0f + tanhf(inner));
}
__device__ __forceinline__ float sigmoidf_(float x) {
    return 1.0f / (1.0f + expf(-x));
}

// ---------------- bf16 split helpers ----------------------------------------
// x = hi + lo + eps, |eps| ~ 2^-16 |x|. Packs pairs (k even in low 16 bits).
__device__ __forceinline__ void split2(float x0, float x1, uint32_t& hp, uint32_t& lp) {
    __nv_bfloat162 h = __floats2bfloat162_rn(x0, x1);
    float r0 = x0 - __bfloat162float(__low2bfloat16(h));
    float r1 = x1 - __bfloat162float(__high2bfloat16(h));
    __nv_bfloat162 l = __floats2bfloat162_rn(r0, r1);
    hp = *reinterpret_cast<uint32_t*>(&h);
    lp = *reinterpret_cast<uint32_t*>(&l);
}

__device__ __forceinline__ void mma16(float* d, const uint32_t* a, const uint32_t* b) {
    asm volatile(
        "mma.sync.aligned.m16n8k16.row.col.f32.bf16.bf16.f32 "
        "{%0,%1,%2,%3}, {%4,%5,%6,%7}, {%8,%9}, {%0,%1,%2,%3};"
        : "+f"(d[0]), "+f"(d[1]), "+f"(d[2]), "+f"(d[3])
        : "r"(a[0]), "r"(a[1]), "r"(a[2]), "r"(a[3]), "r"(b[0]), "r"(b[1]));
}

// ---------------- K0: phi_projT[r][t] = sum_k f[t][k] Mf[k][r] --------------
__global__ __launch_bounds__(256) void phi_kernel(const float* __restrict__ f,
                                                  const float* __restrict__ Mf) {
    __shared__ float sf[KF];
    int t = blockIdx.x;
    if (threadIdx.x < KF) sf[threadIdx.x] = f[t * KF + threadIdx.x];
    __syncthreads();
    for (int r = threadIdx.x; r < DM; r += 256) {
        float acc = 0.f;
#pragma unroll
        for (int k = 0; k < KF; k++) acc += sf[k] * Mf[k * DM + r];
        g_phiT[(size_t)r * T_LEN + t] = acc;
    }
}

// ---------------- repack: Wq|Wk|Wv|Wg|Mi^T -> g_Wcat, biases -> g_bcat ------
__global__ __launch_bounds__(256) void repack_kernel(const float* __restrict__ Wq,
                                                     const float* __restrict__ Wk,
                                                     const float* __restrict__ Wv,
                                                     const float* __restrict__ Wg,
                                                     const float* __restrict__ Mi,
                                                     const float* __restrict__ bq,
                                                     const float* __restrict__ bk,
                                                     const float* __restrict__ bv,
                                                     const float* __restrict__ bg) {
    int i = blockIdx.x * 256 + threadIdx.x;      // 0 .. 5*2^18-1
    int seg = i >> 18;
    int off = i & ((1 << 18) - 1);
    if (seg < 4) {
        const float* W = (seg == 0) ? Wq : (seg == 1) ? Wk : (seg == 2) ? Wv : Wg;
        g_Wcat[i] = W[off];
    } else {
        int n = off >> 9, k = off & (DM - 1);
        g_Wcat[i] = Mi[(size_t)k * DM + n];      // transpose: row n of Mi^T
    }
    if (i < 4 * DM) {
        int s2 = i >> 9, o2 = i & (DM - 1);
        const float* bp = (s2 == 0) ? bq : (s2 == 1) ? bk : (s2 == 2) ? bv : bg;
        g_bcat[i] = bp[o2];
    }
}

// ---------------- bf16x3 tensor-core GEMM ------------------------------------
// C(MxN) = A(MxK) @ B^T, B stored (N x K) row-major. BN=64, BK=32.
// BM=128: 8 warps 4x2, warp tile 32x32. BM=64: 8 warps 2x4, warp tile 32x16.
// EPI 0: C + optional bias. EPI 1: fused QKVG scatter + U transposed.
// COMBA: A formed as gate*Y + (1-gate)*xt on the fly.
template <int EPI>
__device__ __forceinline__ void epi_store(int row, int col, float v,
                                          const float* bias, float* C, int N) {
    if (EPI == 0) {
        if (bias) v += bias[col];
        C[(size_t)row * N + col] = v;
    } else {
        int seg = col >> 9;
        if (seg == 4) {                       // u-projection, transposed
            g_upT[(size_t)(col - 4 * DM) * (BB * T_LEN) + row] = v;
            return;
        }
        v += g_bcat[col];
        int cc = col & (DM - 1);
        int b = row >> 10, t = row & (T_LEN - 1);
        if (seg == 3) {
            g_gate[(size_t)row * DM + cc] = sigmoidf_(v);
        } else {
            float gv = gelu_tanh(v);
            float* P = (seg == 0) ? g_Q : (seg == 1) ? g_Kb : g_V;
            P[(((size_t)(b * NH + (cc >> 6))) * T_LEN + t) * HD + (cc & 63)] = gv;
        }
    }
}

template <int BM, int EPI, int COMBA>
__global__ __launch_bounds__(256) void mma_gemm(const float* __restrict__ A,
                                                const float* __restrict__ B,
                                                const float* __restrict__ bias,
                                                float* __restrict__ C,
                                                int M, int N, int K) {
    constexpr int NWM = BM / 32;          // warps along M (4 or 2)
    constexpr int NT  = NWM;              // n-subtiles per warp (4 or 2)
    constexpr int S   = 20;               // padded row stride (uint32 pairs)
    __shared__ __align__(16) uint32_t sAh[BM * S];
    __shared__ __align__(16) uint32_t sAl[BM * S];
    __shared__ __align__(16) uint32_t sBh[64 * S];
    __shared__ __align__(16) uint32_t sBl[64 * S];

    const int tid = threadIdx.x;
    const int lane = tid & 31, wid = tid >> 5;
    const int wm = wid % NWM, wn = wid / NWM;
    const int brow = blockIdx.y * BM, bcol = blockIdx.x * 64;
    const int c = lane & 3, r4 = lane >> 2;

    float d[2][NT][4];
#pragma unroll
    for (int mt = 0; mt < 2; mt++)
#pragma unroll
        for (int nt = 0; nt < NT; nt++)
#pragma unroll
            for (int e = 0; e < 4; e++) d[mt][nt][e] = 0.f;

    for (int kt = 0; kt < K; kt += 32) {
        // ---- A tile: BM x 32 fp32 -> packed hi/lo pairs ----
        {
            constexpr int NF4 = BM / 32;                 // float4s per thread (4 or 2)
            int row  = (BM == 128) ? (tid >> 1) : (tid >> 2);
            int koff = (BM == 128) ? ((tid & 1) * 16) : ((tid & 3) * 8);
            uint32_t hbuf[2 * NF4], lbuf[2 * NF4];
#pragma unroll
            for (int q = 0; q < NF4; q++) {
                size_t off = (size_t)(brow + row) * K + kt + koff + q * 4;
                float4 a;
                if (COMBA) {
                    float4 gq = *reinterpret_cast<const float4*>(&g_gate[off]);
                    float4 yq = *reinterpret_cast<const float4*>(&g_Y[off]);
                    float4 xq = *reinterpret_cast<const float4*>(&g_xt[off]);
                    a.x = gq.x * yq.x + (1.f - gq.x) * xq.x;
                    a.y = gq.y * yq.y + (1.f - gq.y) * xq.y;
                    a.z = gq.z * yq.z + (1.f - gq.z) * xq.z;
                    a.w = gq.w * yq.w + (1.f - gq.w) * xq.w;
                } else {
                    a = *reinterpret_cast<const float4*>(&A[off]);
                }
                split2(a.x, a.y, hbuf[q * 2], lbuf[q * 2]);
                split2(a.z, a.w, hbuf[q * 2 + 1], lbuf[q * 2 + 1]);
            }
            int base = row * S + (koff >> 1);
#pragma unroll
            for (int q = 0; q < NF4 / 2; q++) {
                *reinterpret_cast<uint4*>(&sAh[base + q * 4]) =
                    make_uint4(hbuf[q*4], hbuf[q*4+1], hbuf[q*4+2], hbuf[q*4+3]);
                *reinterpret_cast<uint4*>(&sAl[base + q * 4]) =
                    make_uint4(lbuf[q*4], lbuf[q*4+1], lbuf[q*4+2], lbuf[q*4+3]);
            }
        }
        // ---- B tile: 64 x 32 (N x K row-major) ----
        {
            int nrow = tid >> 2, koff = (tid & 3) * 8;
            uint32_t hbuf[4], lbuf[4];
#pragma unroll
            for (int q = 0; q < 2; q++) {
                float4 w = *reinterpret_cast<const float4*>(
                    &B[(size_t)(bcol + nrow) * K + kt + koff + q * 4]);
                split2(w.x, w.y, hbuf[q * 2], lbuf[q * 2]);
                split2(w.z, w.w, hbuf[q * 2 + 1], lbuf[q * 2 + 1]);
            }
            int base = nrow * S + (koff >> 1);
            *reinterpret_cast<uint4*>(&sBh[base]) =
                make_uint4(hbuf[0], hbuf[1], hbuf[2], hbuf[3]);
            *reinterpret_cast<uint4*>(&sBl[base]) =
                make_uint4(lbuf[0], lbuf[1], lbuf[2], lbuf[3]);
        }
        __syncthreads();

#pragma unroll
        for (int ks = 0; ks < 2; ks++) {
            const int kb = ks * 8 + c;
            uint32_t ah[2][4], al[2][4], bh[NT][2], bl[NT][2];
#pragma unroll
            for (int mt = 0; mt < 2; mt++) {
                int m0 = wm * 32 + mt * 16 + r4;
                ah[mt][0] = sAh[m0 * S + kb];
                ah[mt][1] = sAh[(m0 + 8) * S + kb];
                ah[mt][2] = sAh[m0 * S + kb + 4];
                ah[mt][3] = sAh[(m0 + 8) * S + kb + 4];
                al[mt][0] = sAl[m0 * S + kb];
                al[mt][1] = sAl[(m0 + 8) * S + kb];
                al[mt][2] = sAl[m0 * S + kb + 4];
                al[mt][3] = sAl[(m0 + 8) * S + kb + 4];
            }
#pragma unroll
            for (int nt = 0; nt < NT; nt++) {
                int n0 = wn * (NT * 8) + nt * 8 + r4;
                bh[nt][0] = sBh[n0 * S + kb];
                bh[nt][1] = sBh[n0 * S + kb + 4];
                bl[nt][0] = sBl[n0 * S + kb];
                bl[nt][1] = sBl[n0 * S + kb + 4];
            }
#pragma unroll
            for (int mt = 0; mt < 2; mt++)
#pragma unroll
                for (int nt = 0; nt < NT; nt++) {
                    mma16(d[mt][nt], ah[mt], bh[nt]);
                    mma16(d[mt][nt], ah[mt], bl[nt]);
                    mma16(d[mt][nt], al[mt], bh[nt]);
                }
        }
        __syncthreads();
    }

    const int c2 = c * 2;
#pragma unroll
    for (int mt = 0; mt < 2; mt++) {
#pragma unroll
        for (int nt = 0; nt < NT; nt++) {
            int row0 = brow + wm * 32 + mt * 16 + r4;
            int col0 = bcol + wn * (NT * 8) + nt * 8 + c2;
            epi_store<EPI>(row0,     col0,     d[mt][nt][0], bias, C, N);
            epi_store<EPI>(row0,     col0 + 1, d[mt][nt][1], bias, C, N);
            epi_store<EPI>(row0 + 8, col0,     d[mt][nt][2], bias, C, N);
            epi_store<EPI>(row0 + 8, col0 + 1, d[mt][nt][3], bias, C, N);
        }
    }
}

// ---------------- K2: even-tap causal conv ----------------------------------
// z[b,t,r] = 2 * sum_{j even, j<=t} v[j,r] * u[b,t-j,r]
// Thread owns 8 consecutive t = 8*tid .. 8*tid+7. Register sliding window,
// j unrolled x4 (one float4 of compacted even-tap v per block).
__global__ __launch_bounds__(128) void conv_kernel() {
    __shared__ __align__(16) float su[6 + T_LEN + 18];   // su[6+i] = u[i]; size mult of 16B
    __shared__ __align__(16) float sve[T_LEN / 2];       // sve[j/2] = v[j] (even taps)
    int r = blockIdx.x, b = blockIdx.y;
    const float* U = g_upT + (size_t)r * (BB * T_LEN) + b * T_LEN;
    const float* V = g_phiT + (size_t)r * T_LEN;
    for (int t = threadIdx.x; t < T_LEN; t += 128) su[6 + t] = U[t];
    for (int i = threadIdx.x; i < T_LEN / 2; i += 128) sve[i] = V[2 * i];
    __syncthreads();

    const int t0 = threadIdx.x * 8;
    float acc[8] = {0.f, 0.f, 0.f, 0.f, 0.f, 0.f, 0.f, 0.f};

    for (int j0 = 0; j0 < t0; j0 += 8) {
        const float4 vv = *reinterpret_cast<const float4*>(&sve[j0 >> 1]);
        const float* wp = &su[t0 - j0];            // 32B aligned (t0-j0 ≡ 0 mod 8)
        float w[16];
#pragma unroll
        for (int q = 0; q < 4; q++)
            *reinterpret_cast<float4*>(&w[q * 4]) =
                *reinterpret_cast<const float4*>(&wp[q * 4]);
#pragma unroll
        for (int k = 0; k < 8; k++) {
            acc[k] = fmaf(vv.x, w[k + 6], acc[k]);
            acc[k] = fmaf(vv.y, w[k + 4], acc[k]);
            acc[k] = fmaf(vv.z, w[k + 2], acc[k]);
            acc[k] = fmaf(vv.w, w[k + 0], acc[k]);
        }
    }
    // tail: j = t0, t0+2, t0+4, t0+6 with partial acc coverage
#pragma unroll
    for (int jo = 0; jo < 4; jo++) {
        int j = t0 + 2 * jo;
        float vj = sve[j >> 1];
#pragma unroll
        for (int k = 0; k < 8; k++)
            if (k >= 2 * jo) acc[k] += vj * su[6 + k - 2 * jo];
    }
#pragma unroll
    for (int k = 0; k < 8; k++) {
        int t = t0 + k;
        g_z[((size_t)b * T_LEN + t) * DM + r] = 2.f * acc[k];
    }
}

// ---------------- K3: LayerNorm over last dim (512), single pass ------------
__global__ __launch_bounds__(256) void ln_kernel(const float* __restrict__ w,
                                                 const float* __restrict__ bparm) {
    __shared__ float redA[8];
    __shared__ float redB[8];
    __shared__ float bc[2];
    int row = blockIdx.x;
    const float* xr = g_z + (size_t)row * DM;
    float v0 = xr[threadIdx.x];
    float v1 = xr[threadIdx.x + 256];
    float s1 = v0 + v1;
    float s2 = v0 * v0 + v1 * v1;
#pragma unroll
    for (int o = 16; o > 0; o >>= 1) {
        s1 += __shfl_xor_sync(0xffffffffu, s1, o);
        s2 += __shfl_xor_sync(0xffffffffu, s2, o);
    }
    int warp = threadIdx.x >> 5;
    if ((threadIdx.x & 31) == 0) { redA[warp] = s1; redB[warp] = s2; }
    __syncthreads();
    if (threadIdx.x < 32) {
        float a = (threadIdx.x < 8) ? redA[threadIdx.x] : 0.f;
        float bsum = (threadIdx.x < 8) ? redB[threadIdx.x] : 0.f;
#pragma unroll
        for (int o = 4; o > 0; o >>= 1) {
            a += __shfl_xor_sync(0xffffffffu, a, o);
            bsum += __shfl_xor_sync(0xffffffffu, bsum, o);
        }
        if (threadIdx.x == 0) { bc[0] = a; bc[1] = bsum; }
    }
    __syncthreads();
    float mu = bc[0] * (1.0f / DM);
    float var = bc[1] * (1.0f / DM) - mu * mu;
    float inv = rsqrtf(var + 1e-5f);
    float d0 = v0 - mu, d1 = v1 - mu;
    g_xt[(size_t)row * DM + threadIdx.x] = d0 * inv * w[threadIdx.x] + bparm[threadIdx.x];
    g_xt[(size_t)row * DM + threadIdx.x + 256] =
        d1 * inv * w[threadIdx.x + 256] + bparm[threadIdx.x + 256];
}

// ---------------- K5: per-chunk state G_c = V_c^T K_c (64x64) ---------------
__global__ __launch_bounds__(256) void chunkstate_kernel() {
    __shared__ __align__(16) float sV[CHUNK * HD];
    __shared__ __align__(16) float sK[CHUNK * HD];
    int c = blockIdx.x, bh = blockIdx.y;
    const float4* Vp = reinterpret_cast<const float4*>(g_V + ((size_t)bh * T_LEN + c * CHUNK) * HD);
    const float4* Kp = reinterpret_cast<const float4*>(g_Kb + ((size_t)bh * T_LEN + c * CHUNK) * HD);
    for (int i = threadIdx.x; i < CHUNK * HD / 4; i += 256) {
        reinterpret_cast<float4*>(sV)[i] = Vp[i];
        reinterpret_cast<float4*>(sK)[i] = Kp[i];
    }
    __syncthreads();
    int p0 = (threadIdx.x >> 4) * 4, n0 = (threadIdx.x & 15) * 4;
    float acc[4][4];
#pragma unroll
    for (int i = 0; i < 4; i++)
#pragma unroll
        for (int j = 0; j < 4; j++) acc[i][j] = 0.f;
    for (int s = 0; s < CHUNK; s++) {
        float rv[4], rk[4];
#pragma unroll
        for (int i = 0; i < 4; i++) rv[i] = sV[s * HD + p0 + i];
#pragma unroll
        for (int j = 0; j < 4; j++) rk[j] = sK[s * HD + n0 + j];
#pragma unroll
        for (int i = 0; i < 4; i++)
#pragma unroll
            for (int j = 0; j < 4; j++) acc[i][j] += rv[i] * rk[j];
    }
    float* Gp = g_G + ((size_t)bh * NCHUNK + c) * HD * HD;
#pragma unroll
    for (int i = 0; i < 4; i++)
#pragma unroll
        for (int j = 0; j < 4; j++) Gp[(p0 + i) * HD + n0 + j] = acc[i][j];
}

// ---------------- K5b: exclusive prefix over chunks -------------------------
__global__ __launch_bounds__(256) void prefix_kernel() {
    int bh = blockIdx.x;
    int base = blockIdx.y * 512;
    for (int slot = base + threadIdx.x; slot < base + 512; slot += 256) {
        float run = 0.f;
        for (int c = 0; c < NCHUNK; c++) {
            size_t idx = ((size_t)bh * NCHUNK + c) * HD * HD + slot;
            g_H[idx] = run;
            run += g_G[idx];
        }
    }
}

// ---------------- K6: Y_c = tril(Q_c V_c^T) K_c + Q_c H_c -------------------
__global__ __launch_bounds__(256) void attn_kernel() {
    __shared__ __align__(16) float sQ[CHUNK * HD];
    __shared__ __align__(16) float sB[CHUNK * HD];
    __shared__ __align__(16) float sS[CHUNK * CHUNK];
    int c = blockIdx.x, bh = blockIdx.y;
    int b = bh / NH, h = bh % NH;
    const float* Qp = g_Q + ((size_t)bh * T_LEN + c * CHUNK) * HD;
    const float* Vp = g_V + ((size_t)bh * T_LEN + c * CHUNK) * HD;
    const float* Kp = g_Kb + ((size_t)bh * T_LEN + c * CHUNK) * HD;

    for (int i = threadIdx.x; i < CHUNK * HD; i += 256) {
        int t = i / HD, p = i % HD;
        sQ[i] = Qp[i];
        sB[p * CHUNK + t] = Vp[i];
    }
    __syncthreads();

    int i0 = (threadIdx.x >> 4) * 4, j0 = (threadIdx.x & 15) * 4;
    float acc[4][4];
#pragma unroll
    for (int a = 0; a < 4; a++)
#pragma unroll
        for (int bb2 = 0; bb2 < 4; bb2++) acc[a][bb2] = 0.f;
    for (int p = 0; p < HD; p++) {
        float rq[4], rv[4];
#pragma unroll
        for (int a = 0; a < 4; a++) rq[a] = sQ[(i0 + a) * HD + p];
#pragma unroll
        for (int a = 0; a < 4; a++) rv[a] = sB[p * CHUNK + j0 + a];
#pragma unroll
        for (int a = 0; a < 4; a++)
#pragma unroll
            for (int bb2 = 0; bb2 < 4; bb2++) acc[a][bb2] += rq[a] * rv[bb2];
    }
#pragma unroll
    for (int a = 0; a < 4; a++)
#pragma unroll
        for (int bb2 = 0; bb2 < 4; bb2++)
            sS[(i0 + a) * CHUNK + j0 + bb2] = (j0 + bb2 <= i0 + a) ? acc[a][bb2] : 0.f;
    __syncthreads();

    for (int i = threadIdx.x; i < CHUNK * HD; i += 256) sB[i] = Kp[i];
    __syncthreads();

    float acc2[4][4];
#pragma unroll
    for (int a = 0; a < 4; a++)
#pragma unroll
        for (int bb2 = 0; bb2 < 4; bb2++) acc2[a][bb2] = 0.f;
    for (int j = 0; j < CHUNK; j++) {
        float rs[4], rk[4];
#pragma unroll
        for (int a = 0; a < 4; a++) rs[a] = sS[(i0 + a) * CHUNK + j];
#pragma unroll
        for (int a = 0; a < 4; a++) rk[a] = sB[j * HD + j0 + a];
#pragma unroll
        for (int a = 0; a < 4; a++)
#pragma unroll
            for (int bb2 = 0; bb2 < 4; bb2++) acc2[a][bb2] += rs[a] * rk[bb2];
    }
    const float* Hp = g_H + ((size_t)bh * NCHUNK + c) * HD * HD;
    for (int p = 0; p < HD; p++) {
        float rq[4], rh[4];
#pragma unroll
        for (int a = 0; a < 4; a++) rq[a] = sQ[(i0 + a) * HD + p];
#pragma unroll
        for (int a = 0; a < 4; a++) rh[a] = Hp[p * HD + j0 + a];
#pragma unroll
        for (int a = 0; a < 4; a++)
#pragma unroll
            for (int bb2 = 0; bb2 < 4; bb2++) acc2[a][bb2] += rq[a] * rh[bb2];
    }
#pragma unroll
    for (int a = 0; a < 4; a++) {
        int t = c * CHUNK + i0 + a;
#pragma unroll
        for (int bb2 = 0; bb2 < 4; bb2++)
            g_Y[((size_t)b * T_LEN + t) * DM + h * HD + j0 + bb2] = acc2[a][bb2];
    }
}

// ---------------- host launcher ---------------------------------------------
extern "C" void kernel_launch(void* const* d_in, const int* in_sizes, int n_in,
                              void* d_out, int out_size) {
    const float* x   = (const float*)d_in[0];
    const float* flt = (const float*)d_in[1];
    const float* Mi  = (const float*)d_in[2];
    const float* Mf  = (const float*)d_in[3];
    const float* Wq  = (const float*)d_in[4];
    const float* bq  = (const float*)d_in[5];
    const float* Wk  = (const float*)d_in[6];
    const float* bk  = (const float*)d_in[7];
    const float* Wv  = (const float*)d_in[8];
    const float* bv  = (const float*)d_in[9];
    const float* Wg  = (const float*)d_in[10];
    const float* bg  = (const float*)d_in[11];
    const float* Wo  = (const float*)d_in[12];
    const float* bo  = (const float*)d_in[13];
    const float* lnw = (const float*)d_in[14];
    const float* lnb = (const float*)d_in[15];
    float* out = (float*)d_out;

    float* Wcat;
    cudaGetSymbolAddress((void**)&Wcat, g_Wcat);

    const int M = BB * T_LEN;  // 2048

    // 1-2: preprocessing (independent)
    phi_kernel<<<T_LEN, 256>>>(flt, Mf);
    repack_kernel<<<NCAT * DM / 256, 256>>>(Wq, Wk, Wv, Wg, Mi, bq, bk, bv, bg);

    // 3: fused Q|K|V|G|U projection (N = 2560), 640 CTAs
    mma_gemm<128, 1, 0><<<dim3(NCAT / 64, M / 128), 256>>>(x, Wcat, nullptr, nullptr,
                                                           M, NCAT, DM);

    // 4-5: STU conv + layernorm   [launch 4 = profiled slot -> conv evidence]
    conv_kernel<<<dim3(DM, BB), 128>>>();
    ln_kernel<<<M, 256>>>(lnw, lnb);

    // 6-8: chunked linear attention
    chunkstate_kernel<<<dim3(NCHUNK, NBH), 256>>>();
    prefix_kernel<<<dim3(NBH, 8), 256>>>();
    attn_kernel<<<dim3(NCHUNK, NBH), 256>>>();

    // 9: output projection with fused combine, BM=64 tiles (256 CTAs)
    mma_gemm<64, 0, 1><<<dim3(DM / 64, M / 64), 256>>>(nullptr, Wo, bo, out,
                                                       M, DM, DM);
}